// round 6
// baseline (speedup 1.0000x reference)
#include <cuda_runtime.h>
#include <cstddef>

#define GN   100000
#define EMAX 1600000

typedef unsigned long long ull;

// ---------------- device scratch (no allocations allowed) ----------------
__device__ float        g_xl[(size_t)GN * 64];
__device__ float        g_xr[(size_t)GN * 64];
__device__ float        g_e[(size_t)(EMAX + GN) * 4];   // raw attention scores
__device__ unsigned int g_menc[(size_t)GN * 4];          // ordered-encoded max
__device__ float        g_den[(size_t)GN * 4];
__device__ float2       g_mden[(size_t)GN * 4];          // packed {m, 1/(den+eps)}
__device__ float        g_h0[(size_t)GN * 64];
__device__ float        g_h1[(size_t)GN * 64];

// ---------------- helpers ----------------
__device__ __forceinline__ ull pk2(float x, float y) {
    ull r; asm("mov.b64 %0, {%1, %2};" : "=l"(r) : "f"(x), "f"(y)); return r;
}
__device__ __forceinline__ void fma2(ull& d, ull a, ull b) {
    asm("fma.rn.f32x2 %0, %1, %2, %0;" : "+l"(d) : "l"(a), "l"(b));
}
__device__ __forceinline__ float2 upk2(ull v) {
    float2 r; asm("mov.b64 {%0, %1}, %2;" : "=f"(r.x), "=f"(r.y) : "l"(v)); return r;
}
// monotonic float<->uint encode for atomicMax over signed floats
__device__ __forceinline__ unsigned fenc(float f) {
    unsigned u = __float_as_uint(f);
    return u ^ ((unsigned)((int)u >> 31) | 0x80000000u);
}
__device__ __forceinline__ float fdec(unsigned u) {
    unsigned m = ((int)u >= 0) ? 0xFFFFFFFFu : 0x80000000u;
    return __uint_as_float(u ^ m);
}

__global__ void zero_k(float4* p, int n4) {
    int i = blockIdx.x * 256 + threadIdx.x;
    if (i < n4) p[i] = make_float4(0.f, 0.f, 0.f, 0.f);
}

// ---------------- dual GEMM: XL = X@Wl + bl, XR = X@Wr + br  (OUT = 64) ----
// 128-row tile, 256 threads, thread = 2 rows x 16 cols, f32x2 packed FMA.
// xs columns XOR-swizzled by ((r>>1)&7)<<2 so the per-k scalar reads across
// the 8 rp values of a warp land in 8 distinct banks (was 8-way conflicted).
template<int CIN>
__global__ void __launch_bounds__(256) gemm_xlxr(
    const float* __restrict__ X,
    const float* __restrict__ Wl, const float* __restrict__ bl,
    const float* __restrict__ Wr, const float* __restrict__ br,
    float* __restrict__ XL, float* __restrict__ XR, int n)
{
    __shared__ __align__(16) float xs[128][64];
    __shared__ __align__(16) ull   ws[64][32];
    const int mat = blockIdx.y;
    const float* __restrict__ W = mat ? Wr : Wl;
    const float* __restrict__ B = mat ? br : bl;
    float* __restrict__ Y = mat ? XR : XL;
    const int row0 = blockIdx.x * 128;
    const int tid = threadIdx.x;
    const int rp = tid >> 2, cg = tid & 3;
    const int sw = (rp & 7) << 2;     // read-side swizzle for this thread's rows

    ull acc[2][8];
#pragma unroll
    for (int r = 0; r < 2; r++)
#pragma unroll
        for (int j = 0; j < 8; j++) acc[r][j] = 0ull;

    for (int kc = 0; kc < CIN; kc += 64) {
#pragma unroll
        for (int i = 0; i < 8; i++) {
            int lin = tid + i * 256;
            int r = lin >> 4, c4 = lin & 15;
            int row = row0 + r;
            float4 v = make_float4(0.f, 0.f, 0.f, 0.f);
            if (row < n) v = *(const float4*)&X[(size_t)row * CIN + kc + c4 * 4];
            int col = (c4 * 4) ^ (((r >> 1) & 7) << 2);   // write-side swizzle
            *(float4*)&xs[r][col] = v;
        }
#pragma unroll
        for (int i = 0; i < 4; i++) {
            int lin = tid + i * 256;
            int r = lin >> 4, c4 = lin & 15;
            float4 v = *(const float4*)&W[(size_t)(kc + r) * 64 + c4 * 4];
            float* wsf = (float*)&ws[r][0];
            *(float4*)&wsf[c4 * 4] = v;
        }
        __syncthreads();
#pragma unroll 8
        for (int k = 0; k < 64; k++) {
            int kk = k ^ sw;
            float xa = xs[rp * 2][kk], xb = xs[rp * 2 + 1][kk];
            ull xa2 = pk2(xa, xa), xb2 = pk2(xb, xb);
            const ull* wr_ = &ws[k][cg * 8];
#pragma unroll
            for (int j = 0; j < 8; j++) {
                ull w = wr_[j];
                fma2(acc[0][j], xa2, w);
                fma2(acc[1][j], xb2, w);
            }
        }
        __syncthreads();
    }
#pragma unroll
    for (int r = 0; r < 2; r++) {
        int row = row0 + rp * 2 + r;
        if (row >= n) continue;
        float o[16];
#pragma unroll
        for (int j = 0; j < 8; j++) {
            float2 p = upk2(acc[r][j]);
            int c = cg * 16 + j * 2;
            o[j * 2]     = p.x + B[c];
            o[j * 2 + 1] = p.y + B[c + 1];
        }
        float* dst = &Y[(size_t)row * 64 + cg * 16];
#pragma unroll
        for (int q = 0; q < 4; q++) *(float4*)&dst[q * 4] = *(float4*)&o[q * 4];
    }
}

// ---------------- pass A: edge scores + segment max ----------------
// 4 threads / edge. H=4: thread t = head t (16 ch). H=1: 4 partials + shfl
// reduce with a QUAD-LOCAL mask (last block is partial; full-warp mask would
// name exited lanes -> UB). Edges e >= E are synthesized self-loops.
template<int H>
__global__ void edge_score_k(const int* __restrict__ src, const int* __restrict__ dst,
                             int E, int Et, const float* __restrict__ att)
{
    int idx = blockIdx.x * 256 + threadIdx.x;
    int e = idx >> 2, t = idx & 3;
    if (e >= Et) return;
    int s, d;
    if (e < E) { s = __ldg(&src[e]); d = __ldg(&dst[e]); } else { s = d = e - E; }

    const float4* xl4 = (const float4*)(g_xl + (size_t)s * 64) + t * 4;
    const float4* xr4 = (const float4*)(g_xr + (size_t)d * 64) + t * 4;
    const float4* a4  = (const float4*)att + t * 4;

    float acc = 0.f;
#pragma unroll
    for (int i = 0; i < 4; i++) {
        float4 l = xl4[i], r = xr4[i], w = a4[i];
        float v;
        v = l.x + r.x; acc += ((v > 0.f) ? v : 0.2f * v) * w.x;
        v = l.y + r.y; acc += ((v > 0.f) ? v : 0.2f * v) * w.y;
        v = l.z + r.z; acc += ((v > 0.f) ? v : 0.2f * v) * w.z;
        v = l.w + r.w; acc += ((v > 0.f) ? v : 0.2f * v) * w.w;
    }
    if (H == 1) {
        // all 4 lanes of a valid edge are active together; mask = this quad only
        unsigned qm = 0xFu << (threadIdx.x & 28);
        acc += __shfl_xor_sync(qm, acc, 1);
        acc += __shfl_xor_sync(qm, acc, 2);
        if (t == 0) {
            g_e[e] = acc;
            atomicMax(&g_menc[d], fenc(acc));
        }
    } else {
        g_e[(size_t)e * 4 + t] = acc;
        atomicMax(&g_menc[(size_t)d * 4 + t], fenc(acc));
    }
}

// ---------------- pass B: denominator accumulate (no writeback) ----------
template<int H>
__global__ void edge_exp_k(const int* __restrict__ dst, int E, int Et)
{
    int idx = blockIdx.x * 256 + threadIdx.x;
    if (idx >= Et * H) return;
    int e = (H == 4) ? (idx >> 2) : idx;
    int h = (H == 4) ? (idx & 3) : 0;
    int d = (e < E) ? __ldg(&dst[e]) : e - E;
    float m  = fdec(g_menc[(size_t)d * H + h]);
    float ex = __expf(g_e[idx] - m);
    atomicAdd(&g_den[(size_t)d * H + h], ex);
}

// ---------------- node pass: pack {m, 1/(den+eps)} for pass C ------------
__global__ void node_mden_k(int nH)
{
    int i = blockIdx.x * 256 + threadIdx.x;
    if (i >= nH) return;
    float m = fdec(g_menc[i]);
    float r = 1.0f / (g_den[i] + 1e-16f);   // den >= exp(0) via self-loop: finite
    g_mden[i] = make_float2(m, r);
}

// ---------------- pass C: alpha-weighted scatter (recomputes exp) --------
// 16 threads / edge; quad leader computes alpha once per (edge, head) and
// broadcasts via width-4 shuffle; one float4 gather + one v4 red per lane.
template<int H>
__global__ void edge_scatter_k(const int* __restrict__ src, const int* __restrict__ dst,
                               int E, int Et, float* __restrict__ out)
{
    int idx = blockIdx.x * 256 + threadIdx.x;
    int e = idx >> 4, t = idx & 15;
    if (e >= Et) return;
    int s, d;
    if (e < E) { s = __ldg(&src[e]); d = __ldg(&dst[e]); } else { s = d = e - E; }
    // quads are threadIdx-aligned (256 % 16 == 0) and all 16 lanes of a valid
    // edge are active together
    unsigned qm = 0xFu << (threadIdx.x & 28);
    float alpha;
    if ((t & 3) == 0) {
        int h = (H == 4) ? (t >> 2) : 0;
        float a   = (H == 4) ? g_e[(size_t)e * 4 + h] : g_e[e];
        float2 md = g_mden[(size_t)d * H + h];
        alpha = __expf(a - md.x) * md.y;
    }
    alpha = __shfl_sync(qm, alpha, 0, 4);
    float4 v = *((const float4*)(g_xl + (size_t)s * 64) + t);
    v.x *= alpha; v.y *= alpha; v.z *= alpha; v.w *= alpha;
    float* p = out + (size_t)d * 64 + t * 4;
    asm volatile("red.global.add.v4.f32 [%0], {%1,%2,%3,%4};"
                 :: "l"(p), "f"(v.x), "f"(v.y), "f"(v.z), "f"(v.w) : "memory");
}

// ---------------- node epilogue: +bias, (relu), L1-norm, (L2-norm + relu) ----
// 8 threads / row; shfl reduce with an 8-lane group mask (safe for any n).
template<bool RELU, bool FINAL>
__global__ void epilogue_k(const float* acc, const float* bias, float* out, int n)
{
    int idx = blockIdx.x * 256 + threadIdx.x;
    int row = idx >> 3, t = idx & 7;
    if (row >= n) return;
    unsigned gm = 0xFFu << (threadIdx.x & 24);   // this 8-lane group only
    float4 v0 = *((const float4*)(acc + (size_t)row * 64) + t * 2);
    float4 v1 = *((const float4*)(acc + (size_t)row * 64) + t * 2 + 1);
    float4 b0 = *((const float4*)bias + t * 2);
    float4 b1 = *((const float4*)bias + t * 2 + 1);
    v0.x += b0.x; v0.y += b0.y; v0.z += b0.z; v0.w += b0.w;
    v1.x += b1.x; v1.y += b1.y; v1.z += b1.z; v1.w += b1.w;
    if (RELU) {
        v0.x = fmaxf(v0.x, 0.f); v0.y = fmaxf(v0.y, 0.f);
        v0.z = fmaxf(v0.z, 0.f); v0.w = fmaxf(v0.w, 0.f);
        v1.x = fmaxf(v1.x, 0.f); v1.y = fmaxf(v1.y, 0.f);
        v1.z = fmaxf(v1.z, 0.f); v1.w = fmaxf(v1.w, 0.f);
    }
    float s = fabsf(v0.x) + fabsf(v0.y) + fabsf(v0.z) + fabsf(v0.w)
            + fabsf(v1.x) + fabsf(v1.y) + fabsf(v1.z) + fabsf(v1.w);
    s += __shfl_xor_sync(gm, s, 1);
    s += __shfl_xor_sync(gm, s, 2);
    s += __shfl_xor_sync(gm, s, 4);
    float inv = 1.0f / fmaxf(s, 1e-12f);
    v0.x *= inv; v0.y *= inv; v0.z *= inv; v0.w *= inv;
    v1.x *= inv; v1.y *= inv; v1.z *= inv; v1.w *= inv;
    if (FINAL) {
        float q = v0.x * v0.x + v0.y * v0.y + v0.z * v0.z + v0.w * v0.w
                + v1.x * v1.x + v1.y * v1.y + v1.z * v1.z + v1.w * v1.w;
        q += __shfl_xor_sync(gm, q, 1);
        q += __shfl_xor_sync(gm, q, 2);
        q += __shfl_xor_sync(gm, q, 4);
        float inv2 = 1.0f / fmaxf(sqrtf(q), 1e-12f);
        v0.x = fmaxf(v0.x * inv2, 0.f); v0.y = fmaxf(v0.y * inv2, 0.f);
        v0.z = fmaxf(v0.z * inv2, 0.f); v0.w = fmaxf(v0.w * inv2, 0.f);
        v1.x = fmaxf(v1.x * inv2, 0.f); v1.y = fmaxf(v1.y * inv2, 0.f);
        v1.z = fmaxf(v1.z * inv2, 0.f); v1.w = fmaxf(v1.w * inv2, 0.f);
    }
    *((float4*)(out + (size_t)row * 64) + t * 2)     = v0;
    *((float4*)(out + (size_t)row * 64) + t * 2 + 1) = v1;
}

// ---------------- host orchestration ----------------
extern "C" void kernel_launch(void* const* d_in, const int* in_sizes, int n_in,
                              void* d_out, int out_size)
{
    const float* x = (const float*)d_in[0];
    const int* ei[3] = {(const int*)d_in[1], (const int*)d_in[2], (const int*)d_in[3]};
    int E[3] = {in_sizes[1] / 2, in_sizes[2] / 2, in_sizes[3] / 2};
    const float* P[18];
    for (int i = 0; i < 18; i++) P[i] = (const float*)d_in[4 + i];
    const int n = in_sizes[0] / 128;           // 100000

    float *xl, *xr, *den, *h0, *h1; unsigned* menc;
    cudaGetSymbolAddress((void**)&xl,   g_xl);
    cudaGetSymbolAddress((void**)&xr,   g_xr);
    cudaGetSymbolAddress((void**)&menc, g_menc);
    cudaGetSymbolAddress((void**)&den,  g_den);
    cudaGetSymbolAddress((void**)&h0,   g_h0);
    cudaGetSymbolAddress((void**)&h1,   g_h1);
    float* fout = (float*)d_out;

    const int gemm_gx = (n + 127) / 128;

    // ---- layer 0: CIN=128, H=4, relu, in = x, out = h0 ----
    {
        const int H = 4, Et = E[0] + n;
        const int* s0 = ei[0]; const int* d0 = ei[0] + E[0];
        zero_k<<<(n * H / 4 + 255) / 256, 256>>>((float4*)menc, n * H / 4);
        zero_k<<<(n * H / 4 + 255) / 256, 256>>>((float4*)den,  n * H / 4);
        zero_k<<<(n * 16 + 255) / 256, 256>>>((float4*)h0, n * 16);
        gemm_xlxr<128><<<dim3(gemm_gx, 2), 256>>>(x, P[0], P[1], P[2], P[3], xl, xr, n);
        edge_score_k<4><<<(Et * 4 + 255) / 256, 256>>>(s0, d0, E[0], Et, P[4]);
        edge_exp_k<4><<<(Et * 4 + 255) / 256, 256>>>(d0, E[0], Et);
        node_mden_k<<<(n * H + 255) / 256, 256>>>(n * H);
        edge_scatter_k<4><<<(Et * 16 + 255) / 256, 256>>>(s0, d0, E[0], Et, h0);
        epilogue_k<true, false><<<(n * 8 + 255) / 256, 256>>>(h0, P[5], h0, n);
    }
    // ---- layer 1: CIN=64, H=4, relu, in = h0, out = h1 ----
    {
        const int H = 4, Et = E[1] + n;
        const int* s1 = ei[1]; const int* d1 = ei[1] + E[1];
        zero_k<<<(n * H / 4 + 255) / 256, 256>>>((float4*)menc, n * H / 4);
        zero_k<<<(n * H / 4 + 255) / 256, 256>>>((float4*)den,  n * H / 4);
        zero_k<<<(n * 16 + 255) / 256, 256>>>((float4*)h1, n * 16);
        gemm_xlxr<64><<<dim3(gemm_gx, 2), 256>>>(h0, P[6], P[7], P[8], P[9], xl, xr, n);
        edge_score_k<4><<<(Et * 4 + 255) / 256, 256>>>(s1, d1, E[1], Et, P[10]);
        edge_exp_k<4><<<(Et * 4 + 255) / 256, 256>>>(d1, E[1], Et);
        node_mden_k<<<(n * H + 255) / 256, 256>>>(n * H);
        edge_scatter_k<4><<<(Et * 16 + 255) / 256, 256>>>(s1, d1, E[1], Et, h1);
        epilogue_k<true, false><<<(n * 8 + 255) / 256, 256>>>(h1, P[11], h1, n);
    }
    // ---- layer 2: CIN=64, H=1, final (L1 -> L2 -> relu), in = h1, out = d_out ----
    {
        const int Et = E[2] + n;
        const int* s2 = ei[2]; const int* d2 = ei[2] + E[2];
        zero_k<<<(n / 4 + 255) / 256, 256>>>((float4*)menc, n / 4);
        zero_k<<<(n / 4 + 255) / 256, 256>>>((float4*)den,  n / 4);
        zero_k<<<(n * 16 + 255) / 256, 256>>>((float4*)fout, n * 16);
        gemm_xlxr<64><<<dim3(gemm_gx, 2), 256>>>(h1, P[12], P[13], P[14], P[15], xl, xr, n);
        edge_score_k<1><<<(Et * 4 + 255) / 256, 256>>>(s2, d2, E[2], Et, P[16]);
        edge_exp_k<1><<<(Et + 255) / 256, 256>>>(d2, E[2], Et);
        node_mden_k<<<(n + 255) / 256, 256>>>(n);
        edge_scatter_k<1><<<(Et * 16 + 255) / 256, 256>>>(s2, d2, E[2], Et, fout);
        epilogue_k<false, true><<<(n * 8 + 255) / 256, 256>>>(fout, P[17], fout, n);
    }
}

// round 12
// speedup vs baseline: 1.2154x; 1.2154x over previous
#include <cuda_runtime.h>
#include <cstddef>

#define GN   100000
#define EMAX 1600000

typedef unsigned long long ull;

// ---------------- device scratch (no allocations allowed) ----------------
__device__ float        g_xl[(size_t)GN * 64];
__device__ float        g_xr[(size_t)GN * 64];
__device__ float        g_e[(size_t)(EMAX + GN) * 4];   // raw attention scores
__device__ unsigned int g_menc[(size_t)GN * 4];          // ordered-encoded max
__device__ float        g_den[(size_t)GN * 4];
__device__ float2       g_mden[(size_t)GN * 4];          // packed {m, 1/(den+eps)}
__device__ float        g_h0[(size_t)GN * 64];
__device__ float        g_h1[(size_t)GN * 64];

// ---------------- helpers ----------------
__device__ __forceinline__ ull pk2(float x, float y) {
    ull r; asm("mov.b64 %0, {%1, %2};" : "=l"(r) : "f"(x), "f"(y)); return r;
}
__device__ __forceinline__ void fma2(ull& d, ull a, ull b) {
    asm("fma.rn.f32x2 %0, %1, %2, %0;" : "+l"(d) : "l"(a), "l"(b));
}
__device__ __forceinline__ float2 upk2(ull v) {
    float2 r; asm("mov.b64 {%0, %1}, %2;" : "=f"(r.x), "=f"(r.y) : "l"(v)); return r;
}
// monotonic float<->uint encode for atomicMax over signed floats
__device__ __forceinline__ unsigned fenc(float f) {
    unsigned u = __float_as_uint(f);
    return u ^ ((unsigned)((int)u >> 31) | 0x80000000u);
}
__device__ __forceinline__ float fdec(unsigned u) {
    unsigned m = ((int)u >= 0) ? 0xFFFFFFFFu : 0x80000000u;
    return __uint_as_float(u ^ m);
}

__global__ void zero_k(float4* p, int n4) {
    int i = blockIdx.x * 256 + threadIdx.x;
    if (i < n4) p[i] = make_float4(0.f, 0.f, 0.f, 0.f);
}

// ---------------- dual GEMM: XL = X@Wl + bl, XR = X@Wr + br  (OUT = 64) ----
// v2: 256-row x 64-col tile, 256 threads, thread = 8 rows x 8 cols (4 f32x2).
// Per k: 8 LDS.32 + 4 LDS.64 feed 32 FFMA2 (was 10 LDS per 16 FFMA2) ->
// FMA-bound instead of L1-bound. xs col swizzled by ((r&7)<<2); ws cols
// interleaved {tx, tx+8, tx+16, tx+24} -> conflict-free reads.
template<int CIN>
__global__ void __launch_bounds__(256) gemm_xlxr(
    const float* __restrict__ X,
    const float* __restrict__ Wl, const float* __restrict__ bl,
    const float* __restrict__ Wr, const float* __restrict__ br,
    float* __restrict__ XL, float* __restrict__ XR, int n)
{
    __shared__ __align__(16) float xs[256][32];
    __shared__ __align__(16) ull   ws[32][32];
    const int mat = blockIdx.y;
    const float* __restrict__ W = mat ? Wr : Wl;
    const float* __restrict__ B = mat ? br : bl;
    float* __restrict__ Y = mat ? XR : XL;
    const int row0 = blockIdx.x * 256;
    const int tid = threadIdx.x;
    const int ty = tid >> 3, tx = tid & 7;
    const int sw = (ty & 7) << 2;     // row-group swizzle (constant per thread)

    ull acc[8][4];
#pragma unroll
    for (int q = 0; q < 8; q++)
#pragma unroll
        for (int j = 0; j < 4; j++) acc[q][j] = 0ull;

    for (int kc = 0; kc < CIN; kc += 32) {
        // X tile: 256 rows x 32 cols = 8 float4 / thread, swizzled store
#pragma unroll
        for (int i = 0; i < 8; i++) {
            int lin = tid + i * 256;
            int r = lin >> 3, c4 = lin & 7;
            int row = row0 + r;
            float4 v = make_float4(0.f, 0.f, 0.f, 0.f);
            if (row < n) v = *(const float4*)&X[(size_t)row * CIN + kc + c4 * 4];
            *(float4*)&xs[r][(c4 * 4) ^ ((r & 7) << 2)] = v;
        }
        // W tile: 32 rows x 64 cols = 2 float4 / thread
#pragma unroll
        for (int i = 0; i < 2; i++) {
            int lin = tid + i * 256;
            int r = lin >> 4, c4 = lin & 15;
            float4 v = *(const float4*)&W[(size_t)(kc + r) * 64 + c4 * 4];
            *(float4*)((float*)&ws[r][0] + c4 * 4) = v;
        }
        __syncthreads();
#pragma unroll 4
        for (int k = 0; k < 32; k++) {
            int kk = k ^ sw;
            ull wv[4];
#pragma unroll
            for (int j = 0; j < 4; j++) wv[j] = ws[k][tx + 8 * j];
#pragma unroll
            for (int q = 0; q < 8; q++) {
                float xa = xs[ty + 32 * q][kk];
                ull xa2 = pk2(xa, xa);
#pragma unroll
                for (int j = 0; j < 4; j++) fma2(acc[q][j], xa2, wv[j]);
            }
        }
        __syncthreads();
    }
    // epilogue: +bias, store 4 float2 per row (cols 2*(tx+8j), 2*(tx+8j)+1)
    float2 bb[4];
#pragma unroll
    for (int j = 0; j < 4; j++) bb[j] = *(const float2*)&B[2 * (tx + 8 * j)];
#pragma unroll
    for (int q = 0; q < 8; q++) {
        int row = row0 + ty + 32 * q;
        if (row >= n) continue;
        float* dst = &Y[(size_t)row * 64];
#pragma unroll
        for (int j = 0; j < 4; j++) {
            float2 p = upk2(acc[q][j]);
            p.x += bb[j].x; p.y += bb[j].y;
            *(float2*)&dst[2 * (tx + 8 * j)] = p;
        }
    }
}

// ---------------- pass A: edge scores + segment max ----------------
// 4 threads / edge. H=4: thread t = head t (16 ch). H=1: 4 partials + shfl
// reduce with a QUAD-LOCAL mask (last block is partial; full-warp mask would
// name exited lanes -> UB). Edges e >= E are synthesized self-loops.
template<int H>
__global__ void edge_score_k(const int* __restrict__ src, const int* __restrict__ dst,
                             int E, int Et, const float* __restrict__ att)
{
    int idx = blockIdx.x * 256 + threadIdx.x;
    int e = idx >> 2, t = idx & 3;
    if (e >= Et) return;
    int s, d;
    if (e < E) { s = __ldg(&src[e]); d = __ldg(&dst[e]); } else { s = d = e - E; }

    const float4* xl4 = (const float4*)(g_xl + (size_t)s * 64) + t * 4;
    const float4* xr4 = (const float4*)(g_xr + (size_t)d * 64) + t * 4;
    const float4* a4  = (const float4*)att + t * 4;

    float acc = 0.f;
#pragma unroll
    for (int i = 0; i < 4; i++) {
        float4 l = xl4[i], r = xr4[i], w = a4[i];
        float v;
        v = l.x + r.x; acc += ((v > 0.f) ? v : 0.2f * v) * w.x;
        v = l.y + r.y; acc += ((v > 0.f) ? v : 0.2f * v) * w.y;
        v = l.z + r.z; acc += ((v > 0.f) ? v : 0.2f * v) * w.z;
        v = l.w + r.w; acc += ((v > 0.f) ? v : 0.2f * v) * w.w;
    }
    if (H == 1) {
        // all 4 lanes of a valid edge are active together; mask = this quad only
        unsigned qm = 0xFu << (threadIdx.x & 28);
        acc += __shfl_xor_sync(qm, acc, 1);
        acc += __shfl_xor_sync(qm, acc, 2);
        if (t == 0) {
            g_e[e] = acc;
            atomicMax(&g_menc[d], fenc(acc));
        }
    } else {
        g_e[(size_t)e * 4 + t] = acc;
        atomicMax(&g_menc[(size_t)d * 4 + t], fenc(acc));
    }
}

// ---------------- pass B: denominator accumulate (no writeback) ----------
template<int H>
__global__ void edge_exp_k(const int* __restrict__ dst, int E, int Et)
{
    int idx = blockIdx.x * 256 + threadIdx.x;
    if (idx >= Et * H) return;
    int e = (H == 4) ? (idx >> 2) : idx;
    int h = (H == 4) ? (idx & 3) : 0;
    int d = (e < E) ? __ldg(&dst[e]) : e - E;
    float m  = fdec(g_menc[(size_t)d * H + h]);
    float ex = __expf(g_e[idx] - m);
    atomicAdd(&g_den[(size_t)d * H + h], ex);
}

// ---------------- node pass: pack {m, 1/(den+eps)} for pass C ------------
__global__ void node_mden_k(int nH)
{
    int i = blockIdx.x * 256 + threadIdx.x;
    if (i >= nH) return;
    float m = fdec(g_menc[i]);
    float r = 1.0f / (g_den[i] + 1e-16f);   // den >= exp(0) via self-loop: finite
    g_mden[i] = make_float2(m, r);
}

// ---------------- pass C: alpha-weighted scatter (recomputes exp) --------
// 16 threads / edge; quad leader computes alpha once per (edge, head) and
// broadcasts via width-4 shuffle; one float4 gather + one v4 red per lane.
template<int H>
__global__ void edge_scatter_k(const int* __restrict__ src, const int* __restrict__ dst,
                               int E, int Et, float* __restrict__ out)
{
    int idx = blockIdx.x * 256 + threadIdx.x;
    int e = idx >> 4, t = idx & 15;
    if (e >= Et) return;
    int s, d;
    if (e < E) { s = __ldg(&src[e]); d = __ldg(&dst[e]); } else { s = d = e - E; }
    // quads are threadIdx-aligned (256 % 16 == 0) and all 16 lanes of a valid
    // edge are active together
    unsigned qm = 0xFu << (threadIdx.x & 28);
    float alpha;
    if ((t & 3) == 0) {
        int h = (H == 4) ? (t >> 2) : 0;
        float a   = (H == 4) ? g_e[(size_t)e * 4 + h] : g_e[e];
        float2 md = g_mden[(size_t)d * H + h];
        alpha = __expf(a - md.x) * md.y;
    }
    alpha = __shfl_sync(qm, alpha, 0, 4);
    float4 v = *((const float4*)(g_xl + (size_t)s * 64) + t);
    v.x *= alpha; v.y *= alpha; v.z *= alpha; v.w *= alpha;
    float* p = out + (size_t)d * 64 + t * 4;
    asm volatile("red.global.add.v4.f32 [%0], {%1,%2,%3,%4};"
                 :: "l"(p), "f"(v.x), "f"(v.y), "f"(v.z), "f"(v.w) : "memory");
}

// ---------------- node epilogue: +bias, (relu), L1-norm, (L2-norm + relu) ----
// 8 threads / row; shfl reduce with an 8-lane group mask (safe for any n).
template<bool RELU, bool FINAL>
__global__ void epilogue_k(const float* acc, const float* bias, float* out, int n)
{
    int idx = blockIdx.x * 256 + threadIdx.x;
    int row = idx >> 3, t = idx & 7;
    if (row >= n) return;
    unsigned gm = 0xFFu << (threadIdx.x & 24);   // this 8-lane group only
    float4 v0 = *((const float4*)(acc + (size_t)row * 64) + t * 2);
    float4 v1 = *((const float4*)(acc + (size_t)row * 64) + t * 2 + 1);
    float4 b0 = *((const float4*)bias + t * 2);
    float4 b1 = *((const float4*)bias + t * 2 + 1);
    v0.x += b0.x; v0.y += b0.y; v0.z += b0.z; v0.w += b0.w;
    v1.x += b1.x; v1.y += b1.y; v1.z += b1.z; v1.w += b1.w;
    if (RELU) {
        v0.x = fmaxf(v0.x, 0.f); v0.y = fmaxf(v0.y, 0.f);
        v0.z = fmaxf(v0.z, 0.f); v0.w = fmaxf(v0.w, 0.f);
        v1.x = fmaxf(v1.x, 0.f); v1.y = fmaxf(v1.y, 0.f);
        v1.z = fmaxf(v1.z, 0.f); v1.w = fmaxf(v1.w, 0.f);
    }
    float s = fabsf(v0.x) + fabsf(v0.y) + fabsf(v0.z) + fabsf(v0.w)
            + fabsf(v1.x) + fabsf(v1.y) + fabsf(v1.z) + fabsf(v1.w);
    s += __shfl_xor_sync(gm, s, 1);
    s += __shfl_xor_sync(gm, s, 2);
    s += __shfl_xor_sync(gm, s, 4);
    float inv = 1.0f / fmaxf(s, 1e-12f);
    v0.x *= inv; v0.y *= inv; v0.z *= inv; v0.w *= inv;
    v1.x *= inv; v1.y *= inv; v1.z *= inv; v1.w *= inv;
    if (FINAL) {
        float q = v0.x * v0.x + v0.y * v0.y + v0.z * v0.z + v0.w * v0.w
                + v1.x * v1.x + v1.y * v1.y + v1.z * v1.z + v1.w * v1.w;
        q += __shfl_xor_sync(gm, q, 1);
        q += __shfl_xor_sync(gm, q, 2);
        q += __shfl_xor_sync(gm, q, 4);
        float inv2 = 1.0f / fmaxf(sqrtf(q), 1e-12f);
        v0.x = fmaxf(v0.x * inv2, 0.f); v0.y = fmaxf(v0.y * inv2, 0.f);
        v0.z = fmaxf(v0.z * inv2, 0.f); v0.w = fmaxf(v0.w * inv2, 0.f);
        v1.x = fmaxf(v1.x * inv2, 0.f); v1.y = fmaxf(v1.y * inv2, 0.f);
        v1.z = fmaxf(v1.z * inv2, 0.f); v1.w = fmaxf(v1.w * inv2, 0.f);
    }
    *((float4*)(out + (size_t)row * 64) + t * 2)     = v0;
    *((float4*)(out + (size_t)row * 64) + t * 2 + 1) = v1;
}

// ---------------- host orchestration ----------------
extern "C" void kernel_launch(void* const* d_in, const int* in_sizes, int n_in,
                              void* d_out, int out_size)
{
    const float* x = (const float*)d_in[0];
    const int* ei[3] = {(const int*)d_in[1], (const int*)d_in[2], (const int*)d_in[3]};
    int E[3] = {in_sizes[1] / 2, in_sizes[2] / 2, in_sizes[3] / 2};
    const float* P[18];
    for (int i = 0; i < 18; i++) P[i] = (const float*)d_in[4 + i];
    const int n = in_sizes[0] / 128;           // 100000

    float *xl, *xr, *den, *h0, *h1; unsigned* menc;
    cudaGetSymbolAddress((void**)&xl,   g_xl);
    cudaGetSymbolAddress((void**)&xr,   g_xr);
    cudaGetSymbolAddress((void**)&menc, g_menc);
    cudaGetSymbolAddress((void**)&den,  g_den);
    cudaGetSymbolAddress((void**)&h0,   g_h0);
    cudaGetSymbolAddress((void**)&h1,   g_h1);
    float* fout = (float*)d_out;

    const int gemm_gx = (n + 255) / 256;

    // ---- layer 0: CIN=128, H=4, relu, in = x, out = h0 ----
    {
        const int H = 4, Et = E[0] + n;
        const int* s0 = ei[0]; const int* d0 = ei[0] + E[0];
        zero_k<<<(n * H / 4 + 255) / 256, 256>>>((float4*)menc, n * H / 4);
        zero_k<<<(n * H / 4 + 255) / 256, 256>>>((float4*)den,  n * H / 4);
        zero_k<<<(n * 16 + 255) / 256, 256>>>((float4*)h0, n * 16);
        gemm_xlxr<128><<<dim3(gemm_gx, 2), 256>>>(x, P[0], P[1], P[2], P[3], xl, xr, n);
        edge_score_k<4><<<(Et * 4 + 255) / 256, 256>>>(s0, d0, E[0], Et, P[4]);
        edge_exp_k<4><<<(Et * 4 + 255) / 256, 256>>>(d0, E[0], Et);
        node_mden_k<<<(n * H + 255) / 256, 256>>>(n * H);
        edge_scatter_k<4><<<(Et * 16 + 255) / 256, 256>>>(s0, d0, E[0], Et, h0);
        epilogue_k<true, false><<<(n * 8 + 255) / 256, 256>>>(h0, P[5], h0, n);
    }
    // ---- layer 1: CIN=64, H=4, relu, in = h0, out = h1 ----
    {
        const int H = 4, Et = E[1] + n;
        const int* s1 = ei[1]; const int* d1 = ei[1] + E[1];
        zero_k<<<(n * H / 4 + 255) / 256, 256>>>((float4*)menc, n * H / 4);
        zero_k<<<(n * H / 4 + 255) / 256, 256>>>((float4*)den,  n * H / 4);
        zero_k<<<(n * 16 + 255) / 256, 256>>>((float4*)h1, n * 16);
        gemm_xlxr<64><<<dim3(gemm_gx, 2), 256>>>(h0, P[6], P[7], P[8], P[9], xl, xr, n);
        edge_score_k<4><<<(Et * 4 + 255) / 256, 256>>>(s1, d1, E[1], Et, P[10]);
        edge_exp_k<4><<<(Et * 4 + 255) / 256, 256>>>(d1, E[1], Et);
        node_mden_k<<<(n * H + 255) / 256, 256>>>(n * H);
        edge_scatter_k<4><<<(Et * 16 + 255) / 256, 256>>>(s1, d1, E[1], Et, h1);
        epilogue_k<true, false><<<(n * 8 + 255) / 256, 256>>>(h1, P[11], h1, n);
    }
    // ---- layer 2: CIN=64, H=1, final (L1 -> L2 -> relu), in = h1, out = d_out ----
    {
        const int Et = E[2] + n;
        const int* s2 = ei[2]; const int* d2 = ei[2] + E[2];
        zero_k<<<(n / 4 + 255) / 256, 256>>>((float4*)menc, n / 4);
        zero_k<<<(n / 4 + 255) / 256, 256>>>((float4*)den,  n / 4);
        zero_k<<<(n * 16 + 255) / 256, 256>>>((float4*)fout, n * 16);
        gemm_xlxr<64><<<dim3(gemm_gx, 2), 256>>>(h1, P[12], P[13], P[14], P[15], xl, xr, n);
        edge_score_k<1><<<(Et * 4 + 255) / 256, 256>>>(s2, d2, E[2], Et, P[16]);
        edge_exp_k<1><<<(Et + 255) / 256, 256>>>(d2, E[2], Et);
        node_mden_k<<<(n + 255) / 256, 256>>>(n);
        edge_scatter_k<1><<<(Et * 16 + 255) / 256, 256>>>(s2, d2, E[2], Et, fout);
        epilogue_k<false, true><<<(n * 8 + 255) / 256, 256>>>(fout, P[17], fout, n);
    }
}